// round 3
// baseline (speedup 1.0000x reference)
#include <cuda_runtime.h>
#include <cuda_bf16.h>

#define BB 16
#define TT 512
#define DD 384
#define MAXLEN 4096
#define D4 (DD/4)   // 96 float4 per row

// scratch: token index per (batch, mel position); -1 = invalid (zero-fill)
__device__ int g_tok[BB * MAXLEN];

// Pass 1: per-batch cumsum + searchsorted for all 4096 positions.
// One block per batch, 512 threads.
__global__ void scan_kernel(const int* __restrict__ dur,
                            float* __restrict__ mel_out, int write_mel) {
    __shared__ int s[TT];
    const int b = blockIdx.x;
    const int tid = threadIdx.x;

    s[tid] = dur[b * TT + tid];
    __syncthreads();

    // Hillis-Steele inclusive scan over 512 elements
    #pragma unroll
    for (int off = 1; off < TT; off <<= 1) {
        int v = (tid >= off) ? s[tid - off] : 0;
        __syncthreads();
        s[tid] += v;
        __syncthreads();
    }

    const int mel = s[TT - 1];
    const int lim = (mel < MAXLEN) ? mel : MAXLEN;

    // each thread resolves 8 mel positions (coalesced stores to g_tok)
    #pragma unroll
    for (int k = 0; k < MAXLEN / TT; k++) {
        const int pos = tid + k * TT;
        // searchsorted(cum, pos, side='right'): first i with cum[i] > pos
        int lo = 0, hi = TT;
        while (lo < hi) {
            const int mid = (lo + hi) >> 1;
            if (s[mid] <= pos) lo = mid + 1; else hi = mid;
        }
        if (lo > TT - 1) lo = TT - 1;   // clip
        g_tok[b * MAXLEN + pos] = (pos < lim) ? lo : -1;
    }

    if (write_mel && tid == 0) {
        mel_out[b] = (float)mel;
    }
}

// Pass 2: one warp per mel row, 3 float4 per lane (96 float4 = 1536B/row).
// blockDim = 128 (4 warps = 4 rows per block).
__global__ void expand_kernel(const float4* __restrict__ enc,
                              float4* __restrict__ out) {
    const int warp = threadIdx.x >> 5;
    const int lane = threadIdx.x & 31;
    const int row  = blockIdx.x * 4 + warp;      // [0, BB*MAXLEN)
    const int b    = row >> 12;                  // MAXLEN = 4096

    const int t = g_tok[row];                    // same addr per warp: broadcast
    float4* dst = out + (size_t)row * D4;

    if (t < 0) {
        const float4 z = make_float4(0.f, 0.f, 0.f, 0.f);
        dst[lane]      = z;
        dst[lane + 32] = z;
        dst[lane + 64] = z;
    } else {
        const float4* src = enc + ((size_t)b * TT + t) * D4;
        // issue all loads before stores (MLP)
        const float4 a = src[lane];
        const float4 c = src[lane + 32];
        const float4 d = src[lane + 64];
        dst[lane]      = a;
        dst[lane + 32] = c;
        dst[lane + 64] = d;
    }
}

extern "C" void kernel_launch(void* const* d_in, const int* in_sizes, int n_in,
                              void* d_out, int out_size) {
    const float4* enc = (const float4*)d_in[0];
    const int*    dur = (const int*)d_in[1];
    float*        out = (float*)d_out;

    const long long expanded_elems = (long long)BB * MAXLEN * DD;  // 25,165,824
    const int write_mel = (out_size > expanded_elems) ? 1 : 0;

    scan_kernel<<<BB, TT>>>(dur, out + expanded_elems, write_mel);
    expand_kernel<<<(BB * MAXLEN) / 4, 128>>>(enc, (float4*)d_out);
}

// round 7
// speedup vs baseline: 1.0972x; 1.0972x over previous
#include <cuda_runtime.h>
#include <cuda_bf16.h>

#define BB 16
#define TT 512
#define DD 384
#define D4 96            // float4 per row
#define MAXLEN 4096
#define ROWS 16          // mel rows per block
#define CHUNKS (MAXLEN / ROWS)   // 256 chunks per batch
#define NTHR 256

__global__ void __launch_bounds__(NTHR)
fused_kernel(const int* __restrict__ dur,
             const float4* __restrict__ enc,
             float4* __restrict__ out,
             float* __restrict__ mel_out, int write_mel)
{
    __shared__ int    s_cum[TT];          // inclusive cumsum of durations
    __shared__ int    s_wsum[8];
    __shared__ int    s_tok[ROWS];        // slot index per row, -1 = zero row
    __shared__ int    s_slotTok[ROWS];    // token id per slot
    __shared__ int    s_nd;
    __shared__ float4 s_data[ROWS * D4];  // 24 KB staged source rows

    const int bidx  = blockIdx.x;
    const int b     = bidx >> 8;          // / CHUNKS
    const int chunk = bidx & (CHUNKS - 1);
    const int tid   = threadIdx.x;
    const int lane  = tid & 31;
    const int wid   = tid >> 5;

    // ---------- Phase 1: cumsum of 512 durations (2 per thread) ----------
    int2 d2 = ((const int2*)(dur + b * TT))[tid];
    int v = d2.x + d2.y;                  // pair sum
    #pragma unroll
    for (int off = 1; off < 32; off <<= 1) {
        int n = __shfl_up_sync(0xffffffffu, v, off);
        if (lane >= off) v += n;
    }
    if (lane == 31) s_wsum[wid] = v;
    __syncthreads();
    if (wid == 0) {
        int w = (lane < 8) ? s_wsum[lane] : 0;
        #pragma unroll
        for (int off = 1; off < 8; off <<= 1) {
            int n = __shfl_up_sync(0xffffffffu, w, off);
            if (lane >= off) w += n;
        }
        if (lane < 8) s_wsum[lane] = w;   // inclusive warp sums
    }
    __syncthreads();
    const int base = (wid > 0) ? s_wsum[wid - 1] : 0;
    const int incl = v + base;            // inclusive cumsum at pair end
    s_cum[2 * tid]     = incl - d2.y;
    s_cum[2 * tid + 1] = incl;
    __syncthreads();

    const int mel  = s_cum[TT - 1];
    const int lim  = (mel < MAXLEN) ? mel : MAXLEN;
    const int row0 = chunk * ROWS;

    // ---------- Phase 2: token per row + run-dedupe (warp 0) ----------
    if (wid == 0) {
        int t = 0, valid = 0;
        if (lane < ROWS) {
            const int pos = row0 + lane;
            int lo = 0, hi = TT;
            while (lo < hi) {             // searchsorted(cum, pos, 'right')
                const int mid = (lo + hi) >> 1;
                if (s_cum[mid] <= pos) lo = mid + 1; else hi = mid;
            }
            t = (lo > TT - 1) ? TT - 1 : lo;
            valid = (pos < lim);
        }
        const int tprev  = __shfl_up_sync(0xffffffffu, t, 1);
        const int newflg = valid && (lane == 0 || t != tprev);
        const unsigned m = __ballot_sync(0xffffffffu, newflg);
        if (lane < ROWS) {
            // slot = index of most recent run-start at or below this lane
            const int slot = __popc(m & ((2u << lane) - 1)) - 1;
            s_tok[lane] = valid ? slot : -1;
            if (newflg) s_slotTok[slot] = t;
        }
        if (lane == 0) s_nd = __popc(m);
    }
    __syncthreads();

    // ---------- Phase 3: stage distinct source rows into SMEM ----------
    const int nd = s_nd;
    const float4* encb = enc + (size_t)b * TT * D4;
    for (int i = tid; i < nd * D4; i += NTHR) {
        const int slot = i / D4;
        const int col  = i - slot * D4;
        s_data[i] = encb[(size_t)s_slotTok[slot] * D4 + col];
    }
    __syncthreads();

    // ---------- Phase 4: coalesced streaming write ----------
    float4* dst = out + (size_t)(b * MAXLEN + row0) * D4;
    const float4 z = make_float4(0.f, 0.f, 0.f, 0.f);
    #pragma unroll
    for (int j = 0; j < (ROWS * D4) / NTHR; j++) {   // 6 iterations
        const int idx = j * NTHR + tid;
        const int row = idx / D4;
        const int col = idx - row * D4;
        const int s   = s_tok[row];
        dst[idx] = (s >= 0) ? s_data[s * D4 + col] : z;
    }

    if (write_mel && chunk == 0 && tid == 0) mel_out[b] = (float)mel;
}

extern "C" void kernel_launch(void* const* d_in, const int* in_sizes, int n_in,
                              void* d_out, int out_size) {
    const int*    dur = (const int*)d_in[1];
    const float4* enc = (const float4*)d_in[0];
    float*        out = (float*)d_out;

    const long long expanded_elems = (long long)BB * MAXLEN * DD;  // 25,165,824
    const int write_mel = (out_size > expanded_elems) ? 1 : 0;

    fused_kernel<<<BB * CHUNKS, NTHR>>>(dur, (const float4*)enc,
                                        (float4*)d_out,
                                        out + expanded_elems, write_mel);
}

// round 11
// speedup vs baseline: 1.1000x; 1.0026x over previous
#include <cuda_runtime.h>
#include <cuda_bf16.h>

#define BB 16
#define TT 512
#define DD 384
#define D4 96             // float4 per row
#define MAXLEN 4096
#define ROWS 32           // mel rows per block (4 per warp)
#define CHUNKS (MAXLEN / ROWS)   // 128
#define NTHR 256

__global__ void __launch_bounds__(NTHR)
fused_kernel(const int* __restrict__ dur,
             const float4* __restrict__ enc,
             float4* __restrict__ out,
             float* __restrict__ mel_out, int write_mel)
{
    __shared__ int s_cum[TT];
    __shared__ int s_wsum[8];

    const int bidx  = blockIdx.x;
    const int b     = bidx >> 7;             // / CHUNKS
    const int chunk = bidx & (CHUNKS - 1);
    const int tid   = threadIdx.x;
    const int lane  = tid & 31;
    const int wid   = tid >> 5;

    // ---------- Phase 1: cumsum of 512 durations (2 per thread) ----------
    int2 d2 = ((const int2*)(dur + b * TT))[tid];
    int v = d2.x + d2.y;
    #pragma unroll
    for (int off = 1; off < 32; off <<= 1) {
        int n = __shfl_up_sync(0xffffffffu, v, off);
        if (lane >= off) v += n;
    }
    if (lane == 31) s_wsum[wid] = v;
    __syncthreads();
    if (wid == 0) {
        int w = (lane < 8) ? s_wsum[lane] : 0;
        #pragma unroll
        for (int off = 1; off < 8; off <<= 1) {
            int n = __shfl_up_sync(0xffffffffu, w, off);
            if (lane >= off) w += n;
        }
        if (lane < 8) s_wsum[lane] = w;
    }
    __syncthreads();
    const int base = (wid > 0) ? s_wsum[wid - 1] : 0;
    const int incl = v + base;
    s_cum[2 * tid]     = incl - d2.y;
    s_cum[2 * tid + 1] = incl;
    __syncthreads();

    const int mel  = s_cum[TT - 1];
    const int lim  = (mel < MAXLEN) ? mel : MAXLEN;
    const int row0 = chunk * ROWS + wid * 4;     // this warp's first row

    // ---------- Phase 2: tokens for this warp's 4 rows (lanes 0-3) ----------
    int tok = 0, val = 0;
    if (lane < 4) {
        const int pos = row0 + lane;
        int lo = 0, hi = TT;
        while (lo < hi) {                        // searchsorted(cum,pos,'right')
            const int mid = (lo + hi) >> 1;
            if (s_cum[mid] <= pos) lo = mid + 1; else hi = mid;
        }
        tok = (lo > TT - 1) ? TT - 1 : lo;
        val = (pos < lim);
    }
    const unsigned FULL = 0xffffffffu;
    const int t0 = __shfl_sync(FULL, tok, 0), v0 = __shfl_sync(FULL, val, 0);
    const int t1 = __shfl_sync(FULL, tok, 1), v1 = __shfl_sync(FULL, val, 1);
    const int t2 = __shfl_sync(FULL, tok, 2), v2 = __shfl_sync(FULL, val, 2);
    const int t3 = __shfl_sync(FULL, tok, 3), v3 = __shfl_sync(FULL, val, 3);

    // ---------- Phase 3: direct gather, 2-row batches (6 loads in flight) ----
    const float4* encb = enc + (size_t)b * TT * D4;
    float4*       dst  = out + (size_t)(b * MAXLEN + row0) * D4;
    const float4  z    = make_float4(0.f, 0.f, 0.f, 0.f);

    {
        const float4* sA = encb + (size_t)t0 * D4;
        const float4* sB = encb + (size_t)t1 * D4;
        float4 a0 = sA[lane], a1 = sA[lane + 32], a2 = sA[lane + 64];
        float4 b0 = sB[lane], b1 = sB[lane + 32], b2 = sB[lane + 64];
        dst[lane]            = v0 ? a0 : z;
        dst[lane + 32]       = v0 ? a1 : z;
        dst[lane + 64]       = v0 ? a2 : z;
        dst[D4 + lane]       = v1 ? b0 : z;
        dst[D4 + lane + 32]  = v1 ? b1 : z;
        dst[D4 + lane + 64]  = v1 ? b2 : z;
    }
    {
        const float4* sA = encb + (size_t)t2 * D4;
        const float4* sB = encb + (size_t)t3 * D4;
        float4 a0 = sA[lane], a1 = sA[lane + 32], a2 = sA[lane + 64];
        float4 b0 = sB[lane], b1 = sB[lane + 32], b2 = sB[lane + 64];
        float4* d2p = dst + 2 * D4;
        d2p[lane]            = v2 ? a0 : z;
        d2p[lane + 32]       = v2 ? a1 : z;
        d2p[lane + 64]       = v2 ? a2 : z;
        d2p[D4 + lane]       = v3 ? b0 : z;
        d2p[D4 + lane + 32]  = v3 ? b1 : z;
        d2p[D4 + lane + 64]  = v3 ? b2 : z;
    }

    if (write_mel && chunk == 0 && tid == 0) mel_out[b] = (float)mel;
}

extern "C" void kernel_launch(void* const* d_in, const int* in_sizes, int n_in,
                              void* d_out, int out_size) {
    const float4* enc = (const float4*)d_in[0];
    const int*    dur = (const int*)d_in[1];
    float*        out = (float*)d_out;

    const long long expanded_elems = (long long)BB * MAXLEN * DD;  // 25,165,824
    const int write_mel = (out_size > expanded_elems) ? 1 : 0;

    fused_kernel<<<BB * CHUNKS, NTHR>>>(dur, enc, (float4*)d_out,
                                        out + expanded_elems, write_mel);
}